// round 16
// baseline (speedup 1.0000x reference)
#include <cuda_runtime.h>
#include <cuda_bf16.h>

#define NUM_P 196          // 14*14 patch locations

__device__ float4 gT[81];  // trig-polynomial coefficients (params-only)

// ---------------------------------------------------------------------------
// Classic gate helpers (16 amplitudes in registers, fully unrolled).
// amplitude index bits: 8=wire0, 4=wire1, 2=wire2, 1=wire3
// ---------------------------------------------------------------------------
template <int M>
__device__ __forceinline__ void ry_real(float* a, float2 g) {
#pragma unroll
    for (int i = 0; i < 16; i++)
        if (!(i & M)) {
            const int j = i | M;
            float a0 = a[i], a1 = a[j];
            a[i] = g.x * a0 - g.y * a1;
            a[j] = g.y * a0 + g.x * a1;
        }
}

template <int M>
__device__ __forceinline__ void ry_cplx(float* ar, float* ai, float2 g) {
#pragma unroll
    for (int i = 0; i < 16; i++)
        if (!(i & M)) {
            const int j = i | M;
            float r0 = ar[i], r1 = ar[j];
            ar[i] = g.x * r0 - g.y * r1;
            ar[j] = g.y * r0 + g.x * r1;
            float i0 = ai[i], i1 = ai[j];
            ai[i] = g.x * i0 - g.y * i1;
            ai[j] = g.y * i0 + g.x * i1;
        }
}

template <int MC, int MT>
__device__ __forceinline__ void cnot_real(float* a) {
#pragma unroll
    for (int i = 0; i < 16; i++)
        if ((i & MC) && !(i & MT)) {
            const int j = i | MT;
            float t = a[i]; a[i] = a[j]; a[j] = t;
        }
}

template <int MC, int MT>
__device__ __forceinline__ void cnot_cplx(float* ar, float* ai) {
    cnot_real<MC, MT>(ar);
    cnot_real<MC, MT>(ai);
}

// circuit body: input = per-wire (cos, sin) of phi/2; output = 4 Z expectations
__device__ __forceinline__ float4
run_circuit(const float* cw, const float* sw, const float2* sCS, const float2* sPh) {
    float ar[16], ai[16];
    {
        float f01[4] = { cw[0] * cw[1], cw[0] * sw[1], sw[0] * cw[1], sw[0] * sw[1] };
        float f23[4] = { cw[2] * cw[3], cw[2] * sw[3], sw[2] * cw[3], sw[2] * sw[3] };
#pragma unroll
        for (int hi = 0; hi < 4; hi++)
#pragma unroll
            for (int lo = 0; lo < 4; lo++)
                ar[hi * 4 + lo] = f01[hi] * f23[lo];
    }
    // layer 0 remainder (real); first RY column is merged into the input angles
    cnot_real<8, 4>(ar); cnot_real<4, 2>(ar); cnot_real<2, 1>(ar);
    ry_real<8>(ar, sCS[0]); ry_real<4>(ar, sCS[1]);
    ry_real<2>(ar, sCS[2]); ry_real<1>(ar, sCS[3]);
    cnot_real<4, 8>(ar); cnot_real<2, 4>(ar); cnot_real<1, 2>(ar);
#pragma unroll
    for (int idx = 0; idx < 16; idx++) {
        float2 ph = sPh[idx];
        ai[idx] = ar[idx] * ph.y;
        ar[idx] = ar[idx] * ph.x;
    }
    // layer 1 (complex; final RZ is pure phase -> skipped)
    ry_cplx<8>(ar, ai, sCS[4]); ry_cplx<4>(ar, ai, sCS[5]);
    ry_cplx<2>(ar, ai, sCS[6]); ry_cplx<1>(ar, ai, sCS[7]);
    cnot_cplx<8, 4>(ar, ai); cnot_cplx<4, 2>(ar, ai); cnot_cplx<2, 1>(ar, ai);
    ry_cplx<8>(ar, ai, sCS[8]); ry_cplx<4>(ar, ai, sCS[9]);
    ry_cplx<2>(ar, ai, sCS[10]); ry_cplx<1>(ar, ai, sCS[11]);
    cnot_cplx<4, 8>(ar, ai); cnot_cplx<2, 4>(ar, ai); cnot_cplx<1, 2>(ar, ai);

    float pv[16];
#pragma unroll
    for (int idx = 0; idx < 16; idx++)
        pv[idx] = fmaf(ar[idx], ar[idx], ai[idx] * ai[idx]);

    float a8[8], d8[8];
#pragma unroll
    for (int k = 0; k < 8; k++) { a8[k] = pv[2*k] + pv[2*k+1]; d8[k] = pv[2*k] - pv[2*k+1]; }
    float z3 = ((d8[0] + d8[1]) + (d8[2] + d8[3])) + ((d8[4] + d8[5]) + (d8[6] + d8[7]));
    float b4[4], e4[4];
#pragma unroll
    for (int j = 0; j < 4; j++) { b4[j] = a8[2*j] + a8[2*j+1]; e4[j] = a8[2*j] - a8[2*j+1]; }
    float z2 = (e4[0] + e4[1]) + (e4[2] + e4[3]);
    float z1 = (b4[0] - b4[1]) + (b4[2] - b4[3]);
    float z0 = (b4[0] + b4[1]) - (b4[2] + b4[3]);
    return make_float4(z0, z1, z2, z3);
}

// ---------------------------------------------------------------------------
// Kernel 1: build the 81-term coefficient tensor T (params-only).
// Evaluate the circuit at phi_w in {0, pi/2, pi}^4, then invert the 3-point
// basis per wire: a=(f0+fpi)/2, b=(f0-fpi)/2, c=f_{pi/2}-a  for (1,cos,sin).
// ---------------------------------------------------------------------------
__global__ void __launch_bounds__(128)
qf_basis_kernel(const float* __restrict__ params) {
    __shared__ float2 sCS[12];
    __shared__ float2 sPh[16];
    __shared__ float zs[81][4];

    const int tid = threadIdx.x;
    const int lane = tid & 31, wid = tid >> 5;

    if (wid == 1) {
        if (lane < 16) {              // one RZ phasor per lane
            float prr = 1.f, pii = 0.f;
#pragma unroll
            for (int w = 0; w < 4; w++) {
                float szv, czv;
                __sincosf(0.5f * params[w * 3 + 2], &szv, &czv);
                float sw_ = (lane & (8 >> w)) ? szv : -szv;
                float nr = prr * czv - pii * sw_;
                pii = prr * sw_ + pii * czv;
                prr = nr;
            }
            sPh[lane] = make_float2(prr, pii);
        } else if (lane < 28) {       // 12 RY gate constants (classic {c,s})
            int j = lane - 16;
            int col = j >> 2, wire = j & 3;
            int pidx = (col == 0) ? wire * 3 + 1
                     : (col == 1) ? 12 + wire * 3
                                  : 12 + wire * 3 + 1;
            float s_, c_;
            __sincosf(0.5f * params[pidx], &s_, &c_);
            sCS[j] = make_float2(c_, s_);
        }
    }
    __syncthreads();

    // 81 sample circuits: digit d -> phi in {0, pi/2, pi}; (cos,sin) of phi/2
    if (tid < 81) {
        const float C[3] = { 1.f, 0.70710678118654752f, 0.f };
        const float S[3] = { 0.f, 0.70710678118654752f, 1.f };
        int d0 = tid / 27, d1 = (tid / 9) % 3, d2 = (tid / 3) % 3, d3 = tid % 3;
        float cw[4] = { C[d0], C[d1], C[d2], C[d3] };
        float sw[4] = { S[d0], S[d1], S[d2], S[d3] };
        float4 z = run_circuit(cw, sw, sCS, sPh);
        zs[tid][0] = z.x; zs[tid][1] = z.y; zs[tid][2] = z.z; zs[tid][3] = z.w;
    }

    // 4 inverse-transform rounds, one per wire (stride 1, 3, 9, 27)
#pragma unroll
    for (int st = 1; st <= 27; st *= 3) {
        __syncthreads();
        if (tid < 108) {
            int g = tid >> 2;            // 0..26 group
            int o = tid & 3;             // output component
            int m0 = (g / st) * (st * 3) + (g % st);
            float f0 = zs[m0][o], f1 = zs[m0 + st][o], f2 = zs[m0 + 2 * st][o];
            float av = 0.5f * (f0 + f2);
            float bv = 0.5f * (f0 - f2);
            float cv = f1 - av;
            zs[m0][o] = av; zs[m0 + st][o] = bv; zs[m0 + 2 * st][o] = cv;
        }
    }
    __syncthreads();
    if (tid < 81)
        gT[tid] = make_float4(zs[tid][0], zs[tid][1], zs[tid][2], zs[tid][3]);
}

// ---------------------------------------------------------------------------
// Kernel 2: 392 blocks x 256 threads; block = (patch p, batch half).
// Phase A: redundant per-block stats (single barrier; T loaded concurrently).
// Phase B: z = Sum_m T[m] * prod_w basis_{m_w}(phi_w)  — no circuit at all.
// ---------------------------------------------------------------------------
__global__ void __launch_bounds__(256)
qf_eval_kernel(const float* __restrict__ x,
               const float* __restrict__ params,
               float* __restrict__ out) {
    __shared__ float sh_s[8], sh_q[8];
    __shared__ float4 sT[81];
    __shared__ float sP0[4];

    const int p    = blockIdx.x >> 1;
    const int half = blockIdx.x & 1;
    const int r = p / 14, c = p % 14;
    const int tid = threadIdx.x;
    const int lane = tid & 31, wid = tid >> 5;

    // --- load two samples' 2x2 patches (rows tid and tid+256) ---
    const float* x0 = x + tid * 784 + (2 * r) * 28 + 2 * c;
    const float* x1 = x0 + 256 * 784;
    float w0 = x0[0], w1 = x0[1], w2 = x0[28], w3 = x0[29];
    float y0 = x1[0], y1 = x1[1], y2 = x1[28], y3 = x1[29];

    // --- Phase A: stats over all 512 samples (2048 values) ---
    float s = ((w0 + w1) + (w2 + w3)) + ((y0 + y1) + (y2 + y3));
    float q = (w0 * w0 + w1 * w1 + w2 * w2 + w3 * w3)
            + (y0 * y0 + y1 * y1 + y2 * y2 + y3 * y3);
#pragma unroll
    for (int o = 16; o > 0; o >>= 1) {
        s += __shfl_down_sync(0xffffffffu, s, o);
        q += __shfl_down_sync(0xffffffffu, q, o);
    }
    if (lane == 0) { sh_s[wid] = s; sh_q[wid] = q; }

    // stage T and the merged angle offsets into shared (overlaps reduction)
    if (tid >= 64 && tid < 145) sT[tid - 64] = gT[tid - 64];
    else if (tid >= 145 && tid < 149) sP0[tid - 145] = params[(tid - 145) * 3];
    __syncthreads();

    // redundant final reduce (LDS broadcast; no second barrier)
    float fs = 0.f, fq = 0.f;
#pragma unroll
    for (int i = 0; i < 8; i++) { fs += sh_s[i]; fq += sh_q[i]; }
    const float mean = fs * (1.0f / 2048.0f);
    const float var = fmaxf((fq - fs * mean) * (1.0f / 2047.0f), 0.0f);
    const float inv = __fdividef(3.14159265358979323846f, sqrtf(var) + 1e-8f);

    // --- Phase B: trig-polynomial evaluation ---
    float v0 = half ? y0 : w0, v1 = half ? y1 : w1;
    float v2 = half ? y2 : w2, v3 = half ? y3 : w3;

    float c0, s0, c1, s1, c2, s2, c3, s3;
    __sincosf((v0 - mean) * inv + sP0[0], &s0, &c0);
    __sincosf((v1 - mean) * inv + sP0[1], &s1, &c1);
    __sincosf((v2 - mean) * inv + sP0[2], &s2, &c2);
    __sincosf((v3 - mean) * inv + sP0[3], &s3, &c3);

    // monomial vectors: index a = d_hi*3 + d_lo over basis {1, cos, sin}
    float M01[9] = { 1.f, c1, s1, c0, c0 * c1, c0 * s1, s0, s0 * c1, s0 * s1 };
    float M23[9] = { 1.f, c3, s3, c2, c2 * c3, c2 * s3, s2, s2 * c3, s2 * s3 };

    float4 z = make_float4(0.f, 0.f, 0.f, 0.f);
#pragma unroll
    for (int a = 0; a < 9; a++) {
        float4 in4 = sT[a * 9];
#pragma unroll
        for (int b = 1; b < 9; b++) {
            float4 t = sT[a * 9 + b];
            float mb = M23[b];
            in4.x = fmaf(t.x, mb, in4.x);
            in4.y = fmaf(t.y, mb, in4.y);
            in4.z = fmaf(t.z, mb, in4.z);
            in4.w = fmaf(t.w, mb, in4.w);
        }
        float ma = M01[a];
        if (a == 0) {
            z = in4;
        } else {
            z.x = fmaf(in4.x, ma, z.x);
            z.y = fmaf(in4.y, ma, z.y);
            z.z = fmaf(in4.z, ma, z.z);
            z.w = fmaf(in4.w, ma, z.w);
        }
    }

    const int b_out = half * 256 + tid;
    *reinterpret_cast<float4*>(out + b_out * 784 + p * 4) = z;
}

// ---------------------------------------------------------------------------
extern "C" void kernel_launch(void* const* d_in, const int* in_sizes, int n_in,
                              void* d_out, int out_size) {
    const float* x = (const float*)d_in[0];
    const float* params = (const float*)d_in[1];
    if (n_in >= 2 && in_sizes[0] == 24) {   // robustness vs input ordering
        x = (const float*)d_in[1];
        params = (const float*)d_in[0];
    }
    float* out = (float*)d_out;

    qf_basis_kernel<<<1, 128>>>(params);
    qf_eval_kernel<<<2 * NUM_P, 256>>>(x, params, out);
}